// round 7
// baseline (speedup 1.0000x reference)
#include <cuda_runtime.h>
#include <math.h>

#define BDIM 1024
#define MDIM 65536
#define DDIM 384
#define HDIM 384
#define KTOP 5
#define CEPS 1e-8f
#define NTILE (MDIM / 128)   // 512 m-tiles

// ---------------- static device scratch (no allocs allowed) ----------------
__device__ float g_center[2];
__device__ float g_qn[BDIM];
__device__ float g_mn[MDIM];
__device__ float g_act[MDIM];
__device__ float g_cval[(size_t)BDIM * NTILE * KTOP];   // candidates
__device__ int   g_cidx[(size_t)BDIM * NTILE * KTOP];
__device__ int   g_topk[BDIM * KTOP];
__device__ float g_xproj[(size_t)BDIM * 6 * HDIM];      // [B][6][H]
__device__ float g_gatel[(size_t)BDIM * HDIM];          // gate logits
__device__ float g_WhhT[HDIM * HDIM];                   // W_hh transposed

// ---------------- packed f32x2 helpers ----------------
#define FMA2(d, a, b) \
    asm("fma.rn.f32x2 %0, %1, %2, %0;" : "+l"(d) : "l"(a), "l"(b))

__device__ __forceinline__ unsigned long long dup2(float x) {
    unsigned long long r;
    asm("mov.b64 %0, {%1, %2};" : "=l"(r) : "f"(x), "f"(x));
    return r;
}
__device__ __forceinline__ float2 unpk2(unsigned long long v) {
    float2 r;
    asm("mov.b64 {%0, %1}, %2;" : "=f"(r.x), "=f"(r.y) : "l"(v));
    return r;
}

// ---------------- center of spatial_weights ----------------
__global__ void center_kernel(const float* __restrict__ sw) {
    __shared__ float s0[64], s1[64];
    int t = threadIdx.x;
    float a = 0.f, b = 0.f;
    for (int i = t; i < HDIM; i += 64) { a += sw[i * 2]; b += sw[i * 2 + 1]; }
    s0[t] = a; s1[t] = b;
    __syncthreads();
    for (int s = 32; s > 0; s >>= 1) {
        if (t < s) { s0[t] += s0[t + s]; s1[t] += s1[t + s]; }
        __syncthreads();
    }
    if (t == 0) {
        g_center[0] = s0[0] / (float)HDIM;
        g_center[1] = s1[0] / (float)HDIM;
    }
}

// ---------------- per-memory norm + spatial activation ----------------
__global__ void memstats_kernel(const float* __restrict__ mem,
                                const float* __restrict__ coords) {
    int warp = (blockIdx.x * blockDim.x + threadIdx.x) >> 5;
    int lane = threadIdx.x & 31;
    if (warp >= MDIM) return;
    const float* r = mem + (size_t)warp * DDIM;
    float s = 0.f;
    for (int d = lane; d < DDIM; d += 32) { float v = r[d]; s = fmaf(v, v, s); }
    #pragma unroll
    for (int o = 16; o > 0; o >>= 1) s += __shfl_down_sync(0xffffffffu, s, o);
    if (lane == 0) {
        g_mn[warp] = sqrtf(s);
        float dx = coords[warp * 2]     - g_center[0];
        float dy = coords[warp * 2 + 1] - g_center[1];
        g_act[warp] = 1.0f / (1.0f + sqrtf(dx * dx + dy * dy));
    }
}

__global__ void qstats_kernel(const float* __restrict__ q) {
    int warp = (blockIdx.x * blockDim.x + threadIdx.x) >> 5;
    int lane = threadIdx.x & 31;
    if (warp >= BDIM) return;
    const float* r = q + (size_t)warp * DDIM;
    float s = 0.f;
    for (int d = lane; d < DDIM; d += 32) { float v = r[d]; s = fmaf(v, v, s); }
    #pragma unroll
    for (int o = 16; o > 0; o >>= 1) s += __shfl_down_sync(0xffffffffu, s, o);
    if (lane == 0) g_qn[warp] = sqrtf(s);
}

// ---------------- top-k insertion primitives ----------------
__device__ __forceinline__ bool tk_better(float av, int ai, float bv, int bi) {
    return (av > bv) || (av == bv && ai < bi);
}
__device__ __forceinline__ void tk_insert(float* tv, int* ti, float v, int i) {
    if (!tk_better(v, i, tv[4], ti[4])) return;
    tv[4] = v; ti[4] = i;
    #pragma unroll
    for (int p = 4; p > 0; p--) {
        if (tk_better(tv[p], ti[p], tv[p - 1], ti[p - 1])) {
            float fv = tv[p]; tv[p] = tv[p - 1]; tv[p - 1] = fv;
            int   fi = ti[p]; ti[p] = ti[p - 1]; ti[p - 1] = fi;
        }
    }
}

// ---------------- main GEMM + fused per-tile top-5 ----------------
// Block tile 64q x 128m, 256 threads, per-thread 4q x 8m, K-chunk 16.
// Packed fma.rn.f32x2 inner loop (2x fp32 rate). Double-buffered smem:
// one barrier per chunk; LDG prefetch issued a full chunk ahead.
// grid: x = q-tiles (16, fast), y = m-tiles (512, slow) so all q-tiles of
// one m-tile are co-resident -> mem_vectors tile read from DRAM once.
__global__ __launch_bounds__(256) void gemm_sims_kernel(
        const float* __restrict__ query, const float* __restrict__ mem) {
    __shared__ unsigned long long As2[2][16][68];   // [buf][k][q] dup pairs
    __shared__ float Bs[2][16][132];                // [buf][k][m]

    const int tid = threadIdx.x;
    const int qt  = blockIdx.x * 64;
    const int mtile = blockIdx.y;
    const int mt  = mtile * 128;
    const int tm  = tid & 15;       // m-group
    const int tq  = tid >> 4;       // q-group (4 rows)

    unsigned long long acc[4][4];
    #pragma unroll
    for (int i = 0; i < 4; i++)
        #pragma unroll
        for (int j = 0; j < 4; j++) acc[i][j] = 0ull;

    const int arow = tid >> 2, a4 = tid & 3;
    const float* aptr  = query + (size_t)(qt + arow) * DDIM + a4 * 4;
    const float* bptr0 = mem   + (size_t)(mt + arow) * DDIM + a4 * 4;
    const float* bptr1 = bptr0 + (size_t)64 * DDIM;

    // chunk 0 -> smem[0]
    float4 rA  = *(const float4*)aptr;
    float4 rB0 = *(const float4*)bptr0;
    float4 rB1 = *(const float4*)bptr1;
    As2[0][a4 * 4 + 0][arow] = dup2(rA.x);
    As2[0][a4 * 4 + 1][arow] = dup2(rA.y);
    As2[0][a4 * 4 + 2][arow] = dup2(rA.z);
    As2[0][a4 * 4 + 3][arow] = dup2(rA.w);
    Bs[0][a4 * 4 + 0][arow] = rB0.x;
    Bs[0][a4 * 4 + 1][arow] = rB0.y;
    Bs[0][a4 * 4 + 2][arow] = rB0.z;
    Bs[0][a4 * 4 + 3][arow] = rB0.w;
    Bs[0][a4 * 4 + 0][arow + 64] = rB1.x;
    Bs[0][a4 * 4 + 1][arow + 64] = rB1.y;
    Bs[0][a4 * 4 + 2][arow + 64] = rB1.z;
    Bs[0][a4 * 4 + 3][arow + 64] = rB1.w;
    // prefetch chunk 1 into regs
    rA  = *(const float4*)(aptr  + 16);
    rB0 = *(const float4*)(bptr0 + 16);
    rB1 = *(const float4*)(bptr1 + 16);
    __syncthreads();

    int buf = 0;
    for (int c = 0; c < 24; c++) {
        // stage chunk c+1 into the other buffer (no barrier needed: compute
        // below reads only smem[buf])
        if (c < 23) {
            int nb = buf ^ 1;
            As2[nb][a4 * 4 + 0][arow] = dup2(rA.x);
            As2[nb][a4 * 4 + 1][arow] = dup2(rA.y);
            As2[nb][a4 * 4 + 2][arow] = dup2(rA.z);
            As2[nb][a4 * 4 + 3][arow] = dup2(rA.w);
            Bs[nb][a4 * 4 + 0][arow] = rB0.x;
            Bs[nb][a4 * 4 + 1][arow] = rB0.y;
            Bs[nb][a4 * 4 + 2][arow] = rB0.z;
            Bs[nb][a4 * 4 + 3][arow] = rB0.w;
            Bs[nb][a4 * 4 + 0][arow + 64] = rB1.x;
            Bs[nb][a4 * 4 + 1][arow + 64] = rB1.y;
            Bs[nb][a4 * 4 + 2][arow + 64] = rB1.z;
            Bs[nb][a4 * 4 + 3][arow + 64] = rB1.w;
            if (c < 22) {   // LDG prefetch chunk c+2, a full chunk of cover
                rA  = *(const float4*)(aptr  + (c + 2) * 16);
                rB0 = *(const float4*)(bptr0 + (c + 2) * 16);
                rB1 = *(const float4*)(bptr1 + (c + 2) * 16);
            }
        }

        #pragma unroll
        for (int k = 0; k < 16; k++) {
            ulonglong2 a01 = *(const ulonglong2*)(&As2[buf][k][tq * 4]);
            ulonglong2 a23 = *(const ulonglong2*)(&As2[buf][k][tq * 4 + 2]);
            ulonglong2 b0  = *(const ulonglong2*)(&Bs[buf][k][tm * 4]);
            ulonglong2 b1  = *(const ulonglong2*)(&Bs[buf][k][64 + tm * 4]);
            FMA2(acc[0][0], a01.x, b0.x); FMA2(acc[0][1], a01.x, b0.y);
            FMA2(acc[0][2], a01.x, b1.x); FMA2(acc[0][3], a01.x, b1.y);
            FMA2(acc[1][0], a01.y, b0.x); FMA2(acc[1][1], a01.y, b0.y);
            FMA2(acc[1][2], a01.y, b1.x); FMA2(acc[1][3], a01.y, b1.y);
            FMA2(acc[2][0], a23.x, b0.x); FMA2(acc[2][1], a23.x, b0.y);
            FMA2(acc[2][2], a23.x, b1.x); FMA2(acc[2][3], a23.x, b1.y);
            FMA2(acc[3][0], a23.y, b0.x); FMA2(acc[3][1], a23.y, b0.y);
            FMA2(acc[3][2], a23.y, b1.x); FMA2(acc[3][3], a23.y, b1.y);
        }
        __syncthreads();   // stores to buf^1 visible; buf free for reuse
        buf ^= 1;
    }

    // ---- epilogue: cosine + activation, fused per-tile top-5 ----
    const int m0 = mt + tm * 4;         // first quad base
    const int m1 = mt + 64 + tm * 4;    // second quad base
    float4 mnA = *(const float4*)(&g_mn[m0]);
    float4 mnB = *(const float4*)(&g_mn[m1]);
    float4 acA = *(const float4*)(&g_act[m0]);
    float4 acB = *(const float4*)(&g_act[m1]);
    float mnv[8] = {mnA.x, mnA.y, mnA.z, mnA.w, mnB.x, mnB.y, mnB.z, mnB.w};
    float acv[8] = {acA.x, acA.y, acA.z, acA.w, acB.x, acB.y, acB.z, acB.w};
    int   mix[8] = {m0, m0 + 1, m0 + 2, m0 + 3, m1, m1 + 1, m1 + 2, m1 + 3};

    #pragma unroll
    for (int iq = 0; iq < 4; iq++) {
        int q = qt + tq * 4 + iq;
        float qv = g_qn[q];
        float2 p0 = unpk2(acc[iq][0]);
        float2 p1 = unpk2(acc[iq][1]);
        float2 p2 = unpk2(acc[iq][2]);
        float2 p3 = unpk2(acc[iq][3]);
        float dots[8] = {p0.x, p0.y, p1.x, p1.y, p2.x, p2.y, p3.x, p3.y};

        float tv[5]; int ti[5];
        #pragma unroll
        for (int i = 0; i < 5; i++) { tv[i] = -INFINITY; ti[i] = 0x7fffffff; }
        #pragma unroll
        for (int j = 0; j < 8; j++) {
            float o = dots[j] / fmaxf(qv * mnv[j], CEPS) + acv[j];
            tk_insert(tv, ti, o, mix[j]);
        }
        // butterfly across the 16 threads covering this q-row
        #pragma unroll
        for (int off = 8; off >= 1; off >>= 1) {
            float ov[5]; int oi[5];
            #pragma unroll
            for (int i = 0; i < 5; i++) {
                ov[i] = __shfl_xor_sync(0xffffffffu, tv[i], off);
                oi[i] = __shfl_xor_sync(0xffffffffu, ti[i], off);
            }
            #pragma unroll
            for (int i = 0; i < 5; i++) tk_insert(tv, ti, ov[i], oi[i]);
        }
        if (tm == 0) {
            size_t off = ((size_t)q * NTILE + mtile) * KTOP;
            #pragma unroll
            for (int i = 0; i < 5; i++) { g_cval[off + i] = tv[i]; g_cidx[off + i] = ti[i]; }
        }
    }
}

// ---------------- final top-5 merge over per-tile candidates ----------------
__global__ __launch_bounds__(256) void final_topk_kernel() {
    const int b = blockIdx.x;
    const int tid = threadIdx.x;
    const float* cv = g_cval + (size_t)b * NTILE * KTOP;
    const int*   ci = g_cidx + (size_t)b * NTILE * KTOP;
    const int total = NTILE * KTOP;   // 2560

    float tv[5]; int ti[5];
    #pragma unroll
    for (int i = 0; i < 5; i++) { tv[i] = -INFINITY; ti[i] = 0x7fffffff; }
    for (int m = tid; m < total; m += 256) tk_insert(tv, ti, cv[m], ci[m]);

    __shared__ float sv[256][5];
    __shared__ int   si[256][5];
    #pragma unroll
    for (int i = 0; i < 5; i++) { sv[tid][i] = tv[i]; si[tid][i] = ti[i]; }

    for (int s = 128; s > 0; s >>= 1) {
        __syncthreads();
        if (tid < s) {
            #pragma unroll
            for (int i = 0; i < 5; i++)
                tk_insert(tv, ti, sv[tid + s][i], si[tid + s][i]);
            #pragma unroll
            for (int i = 0; i < 5; i++) { sv[tid][i] = tv[i]; si[tid][i] = ti[i]; }
        }
    }
    if (tid == 0) {
        #pragma unroll
        for (int i = 0; i < 5; i++) g_topk[b * KTOP + i] = ti[i];
    }
}

// ---------------- x_proj / gate GEMM with row gather ----------------
// mode 0: rows = B*6 -> g_xproj (W_ih); mode 1: rows = B -> g_gatel (W_g).
__global__ __launch_bounds__(256) void proj_gemm_kernel(
        const float* __restrict__ query, const float* __restrict__ mem,
        const float* __restrict__ W, const float* __restrict__ bias, int mode) {
    __shared__ const float* sp[32];
    __shared__ float As[16][36];
    __shared__ float Bs[16][132];

    const int tid = threadIdx.x;
    const int rt = blockIdx.y * 32;
    const int ht = blockIdx.x * 128;

    if (tid < 32) {
        int r = rt + tid;
        const float* p;
        if (mode == 0) {
            int b = r / 6, t = r - b * 6;
            p = (t == 0) ? (query + (size_t)b * DDIM)
                         : (mem + (size_t)g_topk[b * KTOP + (t - 1)] * DDIM);
        } else {
            p = query + (size_t)r * DDIM;
        }
        sp[tid] = p;
    }
    __syncthreads();

    const int th = tid & 31;    // 4 h cols
    const int tr = tid >> 5;    // 4 r rows
    float acc[4][4];
    #pragma unroll
    for (int i = 0; i < 4; i++)
        #pragma unroll
        for (int j = 0; j < 4; j++) acc[i][j] = 0.f;

    const int arow = tid >> 2, a4 = tid & 3;
    const bool aload = (tid < 128);
    const float* ap    = aload ? (sp[arow] + a4 * 4) : (const float*)0;
    const float* bptr0 = W + (size_t)(ht + arow) * DDIM + a4 * 4;
    const float* bptr1 = bptr0 + (size_t)64 * DDIM;

    float4 rA = make_float4(0.f, 0.f, 0.f, 0.f);
    if (aload) rA = *(const float4*)ap;
    float4 rB0 = *(const float4*)bptr0;
    float4 rB1 = *(const float4*)bptr1;

    for (int c = 0; c < 24; c++) {
        if (aload) {
            As[a4 * 4 + 0][arow] = rA.x;
            As[a4 * 4 + 1][arow] = rA.y;
            As[a4 * 4 + 2][arow] = rA.z;
            As[a4 * 4 + 3][arow] = rA.w;
        }
        Bs[a4 * 4 + 0][arow] = rB0.x;
        Bs[a4 * 4 + 1][arow] = rB0.y;
        Bs[a4 * 4 + 2][arow] = rB0.z;
        Bs[a4 * 4 + 3][arow] = rB0.w;
        Bs[a4 * 4 + 0][arow + 64] = rB1.x;
        Bs[a4 * 4 + 1][arow + 64] = rB1.y;
        Bs[a4 * 4 + 2][arow + 64] = rB1.z;
        Bs[a4 * 4 + 3][arow + 64] = rB1.w;
        __syncthreads();

        if (c < 23) {
            if (aload) rA = *(const float4*)(ap + (c + 1) * 16);
            rB0 = *(const float4*)(bptr0 + (c + 1) * 16);
            rB1 = *(const float4*)(bptr1 + (c + 1) * 16);
        }

        #pragma unroll
        for (int k = 0; k < 16; k++) {
            float4 a = *(const float4*)(&As[k][tr * 4]);
            float4 b = *(const float4*)(&Bs[k][th * 4]);
            float av[4] = {a.x, a.y, a.z, a.w};
            float bv[4] = {b.x, b.y, b.z, b.w};
            #pragma unroll
            for (int ir = 0; ir < 4; ir++)
                #pragma unroll
                for (int ih = 0; ih < 4; ih++)
                    acc[ir][ih] = fmaf(av[ir], bv[ih], acc[ir][ih]);
        }
        __syncthreads();
    }

    float* out = (mode == 0) ? g_xproj : g_gatel;
    int hbase = ht + th * 4;
    float4 bs = *(const float4*)(&bias[hbase]);
    #pragma unroll
    for (int ir = 0; ir < 4; ir++) {
        int r = rt + tr * 4 + ir;
        float4 o = make_float4(acc[ir][0] + bs.x, acc[ir][1] + bs.y,
                               acc[ir][2] + bs.z, acc[ir][3] + bs.w);
        *(float4*)(&out[(size_t)r * HDIM + hbase]) = o;
    }
}

// ---------------- W_hh transpose ----------------
__global__ void transpose_kernel(const float* __restrict__ W) {
    int idx = blockIdx.x * 256 + threadIdx.x;
    if (idx < HDIM * HDIM) {
        int i = idx / HDIM, j = idx - i * HDIM;
        g_WhhT[idx] = W[j * HDIM + i];   // WhhT[i][j] = W_hh[j][i]
    }
}

// ---------------- fused RNN + gate + output ----------------
// 128 blocks x 8 samples, 384 threads (thread j = hidden unit j).
__global__ __launch_bounds__(384) void rnn_kernel(const float* __restrict__ b_hh,
                                                  float* __restrict__ out) {
    __shared__ float hT[2][HDIM * 8];   // [buf][i*8 + s]
    const int j  = threadIdx.x;
    const int b0 = blockIdx.x * 8;
    const float bh = b_hh[j];

    {   // t = 0: h = tanh(x_0 + b_hh)
        float h[8];
        #pragma unroll
        for (int s = 0; s < 8; s++)
            h[s] = tanhf(g_xproj[(size_t)(b0 + s) * (6 * HDIM) + j] + bh);
        *(float4*)(&hT[0][j * 8])     = make_float4(h[0], h[1], h[2], h[3]);
        *(float4*)(&hT[0][j * 8 + 4]) = make_float4(h[4], h[5], h[6], h[7]);
    }
    __syncthreads();

    int cur = 0;
    for (int t = 1; t < 6; t++) {
        float acc[8];
        #pragma unroll
        for (int s = 0; s < 8; s++)
            acc[s] = g_xproj[(size_t)(b0 + s) * (6 * HDIM) + t * HDIM + j];

        const float* wcol = g_WhhT + j;
        #pragma unroll 4
        for (int i = 0; i < HDIM; i++) {
            float w = wcol[(size_t)i * HDIM];
            float4 ha = *(const float4*)(&hT[cur][i * 8]);
            float4 hb = *(const float4*)(&hT[cur][i * 8 + 4]);
            acc[0] = fmaf(w, ha.x, acc[0]); acc[1] = fmaf(w, ha.y, acc[1]);
            acc[2] = fmaf(w, ha.z, acc[2]); acc[3] = fmaf(w, ha.w, acc[3]);
            acc[4] = fmaf(w, hb.x, acc[4]); acc[5] = fmaf(w, hb.y, acc[5]);
            acc[6] = fmaf(w, hb.z, acc[6]); acc[7] = fmaf(w, hb.w, acc[7]);
        }

        float h[8];
        #pragma unroll
        for (int s = 0; s < 8; s++) h[s] = tanhf(acc[s] + bh);
        *(float4*)(&hT[cur ^ 1][j * 8])     = make_float4(h[0], h[1], h[2], h[3]);
        *(float4*)(&hT[cur ^ 1][j * 8 + 4]) = make_float4(h[4], h[5], h[6], h[7]);
        cur ^= 1;
        __syncthreads();
    }

    #pragma unroll
    for (int s = 0; s < 8; s++) {
        float gl = g_gatel[(size_t)(b0 + s) * HDIM + j];
        float g  = 1.0f / (1.0f + expf(-gl));
        float direct = g_xproj[(size_t)(b0 + s) * (6 * HDIM) + j];
        out[(size_t)(b0 + s) * HDIM + j] = g * hT[cur][j * 8 + s] + (1.0f - g) * direct;
    }
}

// ---------------- launch ----------------
extern "C" void kernel_launch(void* const* d_in, const int* in_sizes, int n_in,
                              void* d_out, int out_size) {
    const float* query  = (const float*)d_in[0];
    const float* mem    = (const float*)d_in[1];
    const float* coords = (const float*)d_in[2];
    const float* sw     = (const float*)d_in[3];
    const float* W_ih   = (const float*)d_in[4];
    const float* b_ih   = (const float*)d_in[5];
    const float* W_hh   = (const float*)d_in[6];
    const float* b_hh   = (const float*)d_in[7];
    const float* W_g    = (const float*)d_in[8];
    const float* b_g    = (const float*)d_in[9];
    float* out = (float*)d_out;

    center_kernel<<<1, 64>>>(sw);
    memstats_kernel<<<(MDIM * 32) / 256, 256>>>(mem, coords);
    qstats_kernel<<<(BDIM * 32) / 256, 256>>>(query);
    transpose_kernel<<<(HDIM * HDIM + 255) / 256, 256>>>(W_hh);
    gemm_sims_kernel<<<dim3(BDIM / 64, NTILE), 256>>>(query, mem);
    final_topk_kernel<<<BDIM, 256>>>();
    proj_gemm_kernel<<<dim3(HDIM / 128, (BDIM * 6) / 32), 256>>>(query, mem, W_ih, b_ih, 0);
    proj_gemm_kernel<<<dim3(HDIM / 128, BDIM / 32), 256>>>(query, mem, W_g, b_g, 1);
    rnn_kernel<<<BDIM / 8, HDIM>>>(b_hh, out);
}

// round 15
// speedup vs baseline: 1.0842x; 1.0842x over previous
#include <cuda_runtime.h>
#include <cuda_bf16.h>
#include <math.h>
#include <stdint.h>

#define BDIM 1024
#define MDIM 65536
#define DDIM 384
#define HDIM 384
#define KTOP 5
#define CEPS 1e-8f
#define NTIL 512                // m-tiles of 128
#define KC2 32                  // K elems per chunk
#define NCHU 12                 // 384/32
#define ROWB 80                 // padded row stride bytes (64B data + 16 pad)
#define NRES 16                 // exact-rescore depth

// ---------------- static device scratch (no allocs allowed) ----------------
__device__ float g_center[2];
__device__ float g_qn[BDIM];
__device__ float g_mn[MDIM];
__device__ float g_act[MDIM];
__device__ __align__(256) __nv_bfloat16 g_qb[(size_t)BDIM * DDIM];
__device__ __align__(256) __nv_bfloat16 g_mb[(size_t)MDIM * DDIM];
__device__ float g_cval[(size_t)BDIM * NTIL * KTOP];
__device__ int   g_cidx[(size_t)BDIM * NTIL * KTOP];
__device__ int   g_topk[BDIM * KTOP];
__device__ float g_xproj[(size_t)BDIM * 6 * HDIM];
__device__ float g_gatel[(size_t)BDIM * HDIM];
__device__ float g_WhhT[HDIM * HDIM];

// ---------------- PTX helpers ----------------
__device__ __forceinline__ uint32_t smem_u32(const void* p) {
    uint32_t a;
    asm("{ .reg .u64 t; cvta.to.shared.u64 t, %1; cvt.u32.u64 %0, t; }"
        : "=r"(a) : "l"(p));
    return a;
}
template <int N>
__device__ __forceinline__ void ca_wait() {
    asm volatile("cp.async.wait_group %0;" :: "n"(N) : "memory");
}
__device__ __forceinline__ void ca_commit() {
    asm volatile("cp.async.commit_group;" ::: "memory");
}
__device__ __forceinline__ void cp16(uint32_t dst, const void* src) {
    asm volatile("cp.async.cg.shared.global [%0], [%1], 16;"
                 :: "r"(dst), "l"(src) : "memory");
}
__device__ __forceinline__ void ldsm4(uint32_t* r, uint32_t addr) {
    asm volatile("ldmatrix.sync.aligned.m8n8.x4.shared.b16 {%0,%1,%2,%3}, [%4];"
        : "=r"(r[0]), "=r"(r[1]), "=r"(r[2]), "=r"(r[3]) : "r"(addr));
}
__device__ __forceinline__ void mma16816(float* d, const uint32_t* a, const uint32_t* b) {
    asm volatile("mma.sync.aligned.m16n8k16.row.col.f32.bf16.bf16.f32 "
        "{%0,%1,%2,%3}, {%4,%5,%6,%7}, {%8,%9}, {%0,%1,%2,%3};"
        : "+f"(d[0]), "+f"(d[1]), "+f"(d[2]), "+f"(d[3])
        : "r"(a[0]), "r"(a[1]), "r"(a[2]), "r"(a[3]), "r"(b[0]), "r"(b[1]));
}

// ---------------- bf16 convert prep ----------------
__global__ void conv_mem_kernel(const float* __restrict__ src) {
    size_t i = (size_t)blockIdx.x * 256 + threadIdx.x;
    if (i < (size_t)MDIM * DDIM) g_mb[i] = __float2bfloat16(src[i]);
}
__global__ void conv_q_kernel(const float* __restrict__ src) {
    size_t i = (size_t)blockIdx.x * 256 + threadIdx.x;
    if (i < (size_t)BDIM * DDIM) g_qb[i] = __float2bfloat16(src[i]);
}

// ---------------- center / stats ----------------
__global__ void center_kernel(const float* __restrict__ sw) {
    __shared__ float s0[64], s1[64];
    int t = threadIdx.x;
    float a = 0.f, b = 0.f;
    for (int i = t; i < HDIM; i += 64) { a += sw[i * 2]; b += sw[i * 2 + 1]; }
    s0[t] = a; s1[t] = b;
    __syncthreads();
    for (int s = 32; s > 0; s >>= 1) {
        if (t < s) { s0[t] += s0[t + s]; s1[t] += s1[t + s]; }
        __syncthreads();
    }
    if (t == 0) {
        g_center[0] = s0[0] / (float)HDIM;
        g_center[1] = s1[0] / (float)HDIM;
    }
}

__global__ void memstats_kernel(const float* __restrict__ mem,
                                const float* __restrict__ coords) {
    int warp = (blockIdx.x * blockDim.x + threadIdx.x) >> 5;
    int lane = threadIdx.x & 31;
    if (warp >= MDIM) return;
    const float* r = mem + (size_t)warp * DDIM;
    float s = 0.f;
    for (int d = lane; d < DDIM; d += 32) { float v = r[d]; s = fmaf(v, v, s); }
    #pragma unroll
    for (int o = 16; o > 0; o >>= 1) s += __shfl_down_sync(0xffffffffu, s, o);
    if (lane == 0) {
        g_mn[warp] = sqrtf(s);
        float dx = coords[warp * 2]     - g_center[0];
        float dy = coords[warp * 2 + 1] - g_center[1];
        g_act[warp] = 1.0f / (1.0f + sqrtf(dx * dx + dy * dy));
    }
}

__global__ void qstats_kernel(const float* __restrict__ q) {
    int warp = (blockIdx.x * blockDim.x + threadIdx.x) >> 5;
    int lane = threadIdx.x & 31;
    if (warp >= BDIM) return;
    const float* r = q + (size_t)warp * DDIM;
    float s = 0.f;
    for (int d = lane; d < DDIM; d += 32) { float v = r[d]; s = fmaf(v, v, s); }
    #pragma unroll
    for (int o = 16; o > 0; o >>= 1) s += __shfl_down_sync(0xffffffffu, s, o);
    if (lane == 0) g_qn[warp] = sqrtf(s);
}

// ---------------- top-k primitives ----------------
__device__ __forceinline__ bool tk_better(float av, int ai, float bv, int bi) {
    return (av > bv) || (av == bv && ai < bi);
}
__device__ __forceinline__ void tk_insert(float* tv, int* ti, float v, int i) {
    if (!tk_better(v, i, tv[4], ti[4])) return;
    tv[4] = v; ti[4] = i;
    #pragma unroll
    for (int p = 4; p > 0; p--) {
        if (tk_better(tv[p], ti[p], tv[p - 1], ti[p - 1])) {
            float fv = tv[p]; tv[p] = tv[p - 1]; tv[p - 1] = fv;
            int   fi = ti[p]; ti[p] = ti[p - 1]; ti[p - 1] = fi;
        }
    }
}
__device__ __forceinline__ void tk_insert16(float* tv, int* ti, float v, int i) {
    if (!tk_better(v, i, tv[NRES - 1], ti[NRES - 1])) return;
    tv[NRES - 1] = v; ti[NRES - 1] = i;
    #pragma unroll
    for (int p = NRES - 1; p > 0; p--) {
        if (tk_better(tv[p], ti[p], tv[p - 1], ti[p - 1])) {
            float fv = tv[p]; tv[p] = tv[p - 1]; tv[p - 1] = fv;
            int   fi = ti[p]; ti[p] = ti[p - 1]; ti[p - 1] = fi;
        }
    }
}

// ---------------- mma.sync bf16 sims GEMM (filter) + fused top-5 ----------------
// CTA: 128q x 128m, 8 warps (2q x 4m), warp tile 64x32, mma m16n8k16 bf16.
// Sims are bf16-precision CANDIDATE scores only; exact fp32 rescore happens in
// final_topk_kernel, so GEMM noise (sigma~1e-4) cannot affect final picks.
#define A_HI 0
#define B_HI 10240
#define BUFSZ2 20480
#define SMEM_G (2 * BUFSZ2)

__device__ __forceinline__ void load_chunk2(uint32_t bufb, int qt, int mt, int c) {
    const int tid = threadIdx.x;
    const int koff = c * KC2;
    #pragma unroll
    for (int it = 0; it < 2; it++) {
        int idx = tid + it * 256;
        int r = idx >> 2, u = idx & 3;
        uint32_t d = bufb + r * ROWB + u * 16;
        size_t gq = (size_t)(qt + r) * DDIM + koff + u * 8;
        size_t gm = (size_t)(mt + r) * DDIM + koff + u * 8;
        cp16(d + A_HI, g_qb + gq);
        cp16(d + B_HI, g_mb + gm);
    }
}

extern "C" __global__ __launch_bounds__(256, 1)
void mma_gemm_kernel() {
    extern __shared__ __align__(128) char smem[];
    const uint32_t sb = smem_u32(smem);
    const int tid = threadIdx.x;
    const int w = tid >> 5, lane = tid & 31;
    const int wq = w >> 2, wm = w & 3;
    const int g = lane >> 2, c4 = lane & 3;
    const int qt = blockIdx.x * 128;
    const int mt = blockIdx.y * 128;

    const int a_row = ((lane & 8) ? 8 : 0) + (lane & 7);
    const int a_kb  = (lane & 16) ? 16 : 0;
    const int b_row = ((lane >> 4) & 1) * 8 + (lane & 7);
    const int b_kb  = ((lane >> 3) & 1) * 16;

    uint32_t aoff[4], boff[2];
    #pragma unroll
    for (int i = 0; i < 4; i++)
        aoff[i] = (wq * 64 + i * 16 + a_row) * ROWB + a_kb;
    #pragma unroll
    for (int j2 = 0; j2 < 2; j2++)
        boff[j2] = (wm * 32 + j2 * 16 + b_row) * ROWB + b_kb;

    float acc[4][4][4];
    #pragma unroll
    for (int i = 0; i < 4; i++)
        #pragma unroll
        for (int j = 0; j < 4; j++)
            #pragma unroll
            for (int e = 0; e < 4; e++) acc[i][j][e] = 0.f;

    load_chunk2(sb, qt, mt, 0);           ca_commit();
    load_chunk2(sb + BUFSZ2, qt, mt, 1);  ca_commit();

    for (int c = 0; c < NCHU; c++) {
        if (c < NCHU - 1) ca_wait<1>(); else ca_wait<0>();
        __syncthreads();
        uint32_t bufb = sb + (c & 1) * BUFSZ2;

        #pragma unroll
        for (int s = 0; s < 2; s++) {
            const uint32_t ss = s * 32;
            uint32_t aH[4][4];
            #pragma unroll
            for (int i = 0; i < 4; i++)
                ldsm4(aH[i], bufb + A_HI + aoff[i] + ss);
            uint32_t bH[4][2];
            #pragma unroll
            for (int j2 = 0; j2 < 2; j2++) {
                uint32_t r[4];
                ldsm4(r, bufb + B_HI + boff[j2] + ss);
                bH[2 * j2][0] = r[0]; bH[2 * j2][1] = r[1];
                bH[2 * j2 + 1][0] = r[2]; bH[2 * j2 + 1][1] = r[3];
            }
            #pragma unroll
            for (int i = 0; i < 4; i++)
                #pragma unroll
                for (int j = 0; j < 4; j++)
                    mma16816(acc[i][j], aH[i], bH[j]);
        }
        __syncthreads();
        if (c + 2 < NCHU) { load_chunk2(bufb, qt, mt, c + 2); ca_commit(); }
    }

    // ---- epilogue: cosine + act (noisy), per-row top-5, hierarchical merge ----
    float* s_qn  = (float*)smem;               // 128
    float* s_mn  = s_qn + 128;                 // 128
    float* s_act = s_mn + 128;                 // 128
    float* scv   = s_act + 128;                // 128*4*5
    int*   sci   = (int*)(scv + 128 * 4 * 5);  // 128*4*5

    for (int i2 = tid; i2 < 128; i2 += 256) {
        s_qn[i2]  = g_qn[qt + i2];
        s_mn[i2]  = g_mn[mt + i2];
        s_act[i2] = g_act[mt + i2];
    }
    __syncthreads();

    #pragma unroll
    for (int i = 0; i < 4; i++)
        #pragma unroll
        for (int half = 0; half < 2; half++) {
            int rloc = wq * 64 + i * 16 + g + half * 8;
            float qn = s_qn[rloc];
            float tv[5]; int ti[5];
            #pragma unroll
            for (int k = 0; k < 5; k++) { tv[k] = -INFINITY; ti[k] = 0x7fffffff; }
            #pragma unroll
            for (int j = 0; j < 4; j++)
                #pragma unroll
                for (int e = 0; e < 2; e++) {
                    int nl = wm * 32 + j * 8 + c4 * 2 + e;
                    float v = acc[i][j][half * 2 + e];
                    float o = v / fmaxf(qn * s_mn[nl], CEPS) + s_act[nl];
                    tk_insert(tv, ti, o, mt + nl);
                }
            #pragma unroll
            for (int off = 1; off <= 2; off <<= 1) {
                float ov[5]; int oi[5];
                #pragma unroll
                for (int k = 0; k < 5; k++) {
                    ov[k] = __shfl_xor_sync(0xffffffffu, tv[k], off);
                    oi[k] = __shfl_xor_sync(0xffffffffu, ti[k], off);
                }
                #pragma unroll
                for (int k = 0; k < 5; k++) tk_insert(tv, ti, ov[k], oi[k]);
            }
            if (c4 == 0) {
                int base = (rloc * 4 + wm) * 5;
                #pragma unroll
                for (int k = 0; k < 5; k++) { scv[base + k] = tv[k]; sci[base + k] = ti[k]; }
            }
        }
    __syncthreads();

    if (tid < 128) {
        float tv[5]; int ti[5];
        #pragma unroll
        for (int k = 0; k < 5; k++) { tv[k] = -INFINITY; ti[k] = 0x7fffffff; }
        #pragma unroll
        for (int wm2 = 0; wm2 < 4; wm2++) {
            int base = (tid * 4 + wm2) * 5;
            #pragma unroll
            for (int k = 0; k < 5; k++) tk_insert(tv, ti, scv[base + k], sci[base + k]);
        }
        size_t off = ((size_t)(qt + tid) * NTIL + blockIdx.y) * KTOP;
        #pragma unroll
        for (int k = 0; k < 5; k++) { g_cval[off + k] = tv[k]; g_cidx[off + k] = ti[k]; }
    }
}

// ---------------- final: noisy top-16 merge + EXACT fp32 rescore + top-5 ----------------
__global__ __launch_bounds__(256) void final_topk_kernel(
        const float* __restrict__ query, const float* __restrict__ mem) {
    const int b = blockIdx.x;
    const int tid = threadIdx.x;
    const float* cv = g_cval + (size_t)b * NTIL * KTOP;
    const int*   ci = g_cidx + (size_t)b * NTIL * KTOP;
    const int total = NTIL * KTOP;   // 2560

    // phase 1: merge 2560 noisy candidates to global noisy top-16
    float tv[NRES]; int ti[NRES];
    #pragma unroll
    for (int i = 0; i < NRES; i++) { tv[i] = -INFINITY; ti[i] = 0x7fffffff; }
    for (int m = tid; m < total; m += 256) tk_insert16(tv, ti, cv[m], ci[m]);

    __shared__ float sv[256][NRES];
    __shared__ int   si[256][NRES];
    #pragma unroll
    for (int i = 0; i < NRES; i++) { sv[tid][i] = tv[i]; si[tid][i] = ti[i]; }

    for (int s = 128; s > 0; s >>= 1) {
        __syncthreads();
        if (tid < s) {
            #pragma unroll
            for (int i = 0; i < NRES; i++)
                tk_insert16(tv, ti, sv[tid + s][i], si[tid + s][i]);
            #pragma unroll
            for (int i = 0; i < NRES; i++) { sv[tid][i] = tv[i]; si[tid][i] = ti[i]; }
        }
    }
    __shared__ int   cand_i[NRES];
    __shared__ float cand_e[NRES];
    __syncthreads();
    if (tid == 0) {
        #pragma unroll
        for (int k = 0; k < NRES; k++) cand_i[k] = ti[k];
    }
    __syncthreads();

    // phase 2: exact fp32 rescore of the 16 candidates
    const int w = tid >> 5, lane = tid & 31;
    const float* qp = query + (size_t)b * DDIM;
    for (int c = w; c < NRES; c += 8) {
        int idx = cand_i[c];
        const float* mp = mem + (size_t)idx * DDIM;
        float s = 0.f;
        for (int d = lane; d < DDIM; d += 32) s = fmaf(qp[d], mp[d], s);
        #pragma unroll
        for (int o = 16; o > 0; o >>= 1) s += __shfl_down_sync(0xffffffffu, s, o);
        if (lane == 0)
            cand_e[c] = s / fmaxf(g_qn[b] * g_mn[idx], CEPS) + g_act[idx];
    }
    __syncthreads();

    if (tid == 0) {
        float fv[5]; int fi[5];
        #pragma unroll
        for (int k = 0; k < 5; k++) { fv[k] = -INFINITY; fi[k] = 0x7fffffff; }
        #pragma unroll
        for (int k = 0; k < NRES; k++) tk_insert(fv, fi, cand_e[k], cand_i[k]);
        #pragma unroll
        for (int k = 0; k < 5; k++) g_topk[b * KTOP + k] = fi[k];
    }
}

// ---------------- x_proj / gate GEMM with row gather ----------------
__global__ __launch_bounds__(256) void proj_gemm_kernel(
        const float* __restrict__ query, const float* __restrict__ mem,
        const float* __restrict__ W, const float* __restrict__ bias, int mode) {
    __shared__ const float* sp[32];
    __shared__ float As[16][36];
    __shared__ float Bs[16][132];

    const int tid = threadIdx.x;
    const int rt = blockIdx.y * 32;
    const int ht = blockIdx.x * 128;

    if (tid < 32) {
        int r = rt + tid;
        const float* p;
        if (mode == 0) {
            int b = r / 6, t = r - b * 6;
            p = (t == 0) ? (query + (size_t)b * DDIM)
                         : (mem + (size_t)g_topk[b * KTOP + (t - 1)] * DDIM);
        } else {
            p = query + (size_t)r * DDIM;
        }
        sp[tid] = p;
    }
    __syncthreads();

    const int th = tid & 31;
    const int tr = tid >> 5;
    float acc[4][4];
    #pragma unroll
    for (int i = 0; i < 4; i++)
        #pragma unroll
        for (int j = 0; j < 4; j++) acc[i][j] = 0.f;

    const int arow = tid >> 2, a4 = tid & 3;
    const bool aload = (tid < 128);
    const float* ap    = aload ? (sp[arow] + a4 * 4) : (const float*)0;
    const float* bptr0 = W + (size_t)(ht + arow) * DDIM + a4 * 4;
    const float* bptr1 = bptr0 + (size_t)64 * DDIM;

    float4 rA = make_float4(0.f, 0.f, 0.f, 0.f);
    if (aload) rA = *(const float4*)ap;
    float4 rB0 = *(const float4*)bptr0;
    float4 rB1 = *(const float4*)bptr1;

    for (int c = 0; c < 24; c++) {
        if (aload) {
            As[a4 * 4 + 0][arow] = rA.x;
            As[a4 * 4 + 1][arow] = rA.y;
            As[a4 * 4 + 2][arow] = rA.z;
            As[a4 * 4 + 3][arow] = rA.w;
        }
        Bs[a4 * 4 + 0][arow] = rB0.x;
        Bs[a4 * 4 + 1][arow] = rB0.y;
        Bs[a4 * 4 + 2][arow] = rB0.z;
        Bs[a4 * 4 + 3][arow] = rB0.w;
        Bs[a4 * 4 + 0][arow + 64] = rB1.x;
        Bs[a4 * 4 + 1][arow + 64] = rB1.y;
        Bs[a4 * 4 + 2][arow + 64] = rB1.z;
        Bs[a4 * 4 + 3][arow + 64] = rB1.w;
        __syncthreads();

        if (c < 23) {
            if (aload) rA = *(const float4*)(ap + (c + 1) * 16);
            rB0 = *(const float4*)(bptr0 + (c + 1) * 16);
            rB1 = *(const float4*)(bptr1 + (c + 1) * 16);
        }

        #pragma unroll
        for (int k = 0; k < 16; k++) {
            float4 a = *(const float4*)(&As[k][tr * 4]);
            float4 b = *(const float4*)(&Bs[k][th * 4]);
            float av[4] = {a.x, a.y, a.z, a.w};
            float bv[4] = {b.x, b.y, b.z, b.w};
            #pragma unroll
            for (int ir = 0; ir < 4; ir++)
                #pragma unroll
                for (int ih = 0; ih < 4; ih++)
                    acc[ir][ih] = fmaf(av[ir], bv[ih], acc[ir][ih]);
        }
        __syncthreads();
    }

    float* out = (mode == 0) ? g_xproj : g_gatel;
    int hbase = ht + th * 4;
    float4 bs = *(const float4*)(&bias[hbase]);
    #pragma unroll
    for (int ir = 0; ir < 4; ir++) {
        int r = rt + tr * 4 + ir;
        float4 o = make_float4(acc[ir][0] + bs.x, acc[ir][1] + bs.y,
                               acc[ir][2] + bs.z, acc[ir][3] + bs.w);
        *(float4*)(&out[(size_t)r * HDIM + hbase]) = o;
    }
}

// ---------------- W_hh transpose ----------------
__global__ void transpose_kernel(const float* __restrict__ W) {
    int idx = blockIdx.x * 256 + threadIdx.x;
    if (idx < HDIM * HDIM) {
        int i = idx / HDIM, j = idx - i * HDIM;
        g_WhhT[idx] = W[j * HDIM + i];
    }
}

// ---------------- fused RNN + gate + output ----------------
__global__ __launch_bounds__(384) void rnn_kernel(const float* __restrict__ b_hh,
                                                  float* __restrict__ out) {
    __shared__ float hT[2][HDIM * 8];
    const int j  = threadIdx.x;
    const int b0 = blockIdx.x * 8;
    const float bh = b_hh[j];

    {
        float h[8];
        #pragma unroll
        for (int s = 0; s < 8; s++)
            h[s] = tanhf(g_xproj[(size_t)(b0 + s) * (6 * HDIM) + j] + bh);
        *(float4*)(&hT[0][j * 8])     = make_float4(h[0], h[1], h[2], h[3]);
        *(float4*)(&hT[0][j * 8 + 4]) = make_float4(h[4], h[5], h[6], h[7]);
    }
    __syncthreads();

    int cur = 0;
    for (int t = 1; t < 6; t++) {
        float acc[8];
        #pragma unroll
        for (int s = 0; s < 8; s++)
            acc[s] = g_xproj[(size_t)(b0 + s) * (6 * HDIM) + t * HDIM + j];

        const float* wcol = g_WhhT + j;
        #pragma unroll 4
        for (int i = 0; i < HDIM; i++) {
            float w = wcol[(size_t)i * HDIM];
            float4 ha = *(const float4*)(&hT[cur][i * 8]);
            float4 hb = *(const float4*)(&hT[cur][i * 8 + 4]);
            acc[0] = fmaf(w, ha.x, acc[0]); acc[1] = fmaf(w, ha.y, acc[1]);
            acc[2] = fmaf(w, ha.z, acc[2]); acc[3] = fmaf(w, ha.w, acc[3]);
            acc[4] = fmaf(w, hb.x, acc[4]); acc[5] = fmaf(w, hb.y, acc[5]);
            acc[6] = fmaf(w, hb.z, acc[6]); acc[7] = fmaf(w, hb.w, acc[7]);
        }

        float h[8];
        #pragma unroll
        for (int s = 0; s < 8; s++) h[s] = tanhf(acc[s] + bh);
        *(float4*)(&hT[cur ^ 1][j * 8])     = make_float4(h[0], h[1], h[2], h[3]);
        *(float4*)(&hT[cur ^ 1][j * 8 + 4]) = make_float4(h[4], h[5], h[6], h[7]);
        cur ^= 1;
        __syncthreads();
    }

    #pragma unroll
    for (int s = 0; s < 8; s++) {
        float gl = g_gatel[(size_t)(b0 + s) * HDIM + j];
        float g  = 1.0f / (1.0f + expf(-gl));
        float direct = g_xproj[(size_t)(b0 + s) * (6 * HDIM) + j];
        out[(size_t)(b0 + s) * HDIM + j] = g * hT[cur][j * 8 + s] + (1.0f - g) * direct;
    }
}

// ---------------- launch ----------------
extern "C" void kernel_launch(void* const* d_in, const int* in_sizes, int n_in,
                              void* d_out, int out_size) {
    const float* query  = (const float*)d_in[0];
    const float* mem    = (const float*)d_in[1];
    const float* coords = (const float*)d_in[2];
    const float* sw     = (const float*)d_in[3];
    const float* W_ih   = (const float*)d_in[4];
    const float* b_ih   = (const float*)d_in[5];
    const float* W_hh   = (const float*)d_in[6];
    const float* b_hh   = (const float*)d_in[7];
    const float* W_g    = (const float*)d_in[8];
    const float* b_g    = (const float*)d_in[9];
    float* out = (float*)d_out;

    cudaFuncSetAttribute(mma_gemm_kernel,
                         cudaFuncAttributeMaxDynamicSharedMemorySize, SMEM_G);

    center_kernel<<<1, 64>>>(sw);                                              // 0
    conv_mem_kernel<<<(MDIM * DDIM + 255) / 256, 256>>>(mem);                  // 1
    conv_q_kernel<<<(BDIM * DDIM + 255) / 256, 256>>>(query);                  // 2
    memstats_kernel<<<(MDIM * 32) / 256, 256>>>(mem, coords);                  // 3
    qstats_kernel<<<(BDIM * 32) / 256, 256>>>(query);                          // 4
    mma_gemm_kernel<<<dim3(BDIM / 128, MDIM / 128), 256, SMEM_G>>>();          // 5
    final_topk_kernel<<<BDIM, 256>>>(query, mem);                              // 6
    proj_gemm_kernel<<<dim3(HDIM / 128, (BDIM * 6) / 32), 256>>>(query, mem, W_ih, b_ih, 0);
    proj_gemm_kernel<<<dim3(HDIM / 128, BDIM / 32), 256>>>(query, mem, W_g, b_g, 1);
    transpose_kernel<<<(HDIM * HDIM + 255) / 256, 256>>>(W_hh);
    rnn_kernel<<<BDIM / 8, HDIM>>>(b_hh, out);
}